// round 4
// baseline (speedup 1.0000x reference)
#include <cuda_runtime.h>
#include <cuda_bf16.h>
#include <cstdint>

#define B_TOK 32768
#define D_DIM 256
#define H_DIM 8192
#define K_TOP 32

// ---------------- static scratch (no cudaMalloc allowed) ----------------
__device__ __align__(16) __nv_bfloat16 g_xb[(size_t)B_TOK * D_DIM];     // 16 MB
__device__ __align__(16) __nv_bfloat16 g_wb[(size_t)H_DIM * D_DIM];     //  4 MB
__device__ __align__(16) __nv_bfloat16 g_acts[(size_t)B_TOK * H_DIM];   // 512 MB

// ---------------- K0: fp32 -> bf16 conversion ----------------
__global__ void cvt_kernel(const float* __restrict__ x, const float* __restrict__ w) {
    const long long n1 = (long long)B_TOK * D_DIM / 4;   // float4 count for x
    const long long n2 = (long long)H_DIM * D_DIM / 4;   // float4 count for W_enc
    long long i = blockIdx.x * (long long)blockDim.x + threadIdx.x;
    if (i < n1) {
        float4 v = ((const float4*)x)[i];
        __nv_bfloat162* o = (__nv_bfloat162*)g_xb;
        o[2 * i]     = __floats2bfloat162_rn(v.x, v.y);
        o[2 * i + 1] = __floats2bfloat162_rn(v.z, v.w);
    } else if (i < n1 + n2) {
        long long j = i - n1;
        float4 v = ((const float4*)w)[j];
        __nv_bfloat162* o = (__nv_bfloat162*)g_wb;
        o[2 * j]     = __floats2bfloat162_rn(v.x, v.y);
        o[2 * j + 1] = __floats2bfloat162_rn(v.z, v.w);
    }
}

// ---------------- K1: bf16 GEMM  acts[b][h] ~= x[b]·W_enc[h] + b_enc[h] (approx, bf16 out) ----------------
#define BM 128
#define BN 128
#define BK 32
#define APITCH 40   // bf16 elems per smem row (32 + 8 pad); 80B rows, 16B aligned

__global__ void __launch_bounds__(256, 2) enc_gemm_kernel(const float* __restrict__ b_enc) {
    __shared__ __align__(16) __nv_bfloat16 sA[2][BM * APITCH];
    __shared__ __align__(16) __nv_bfloat16 sB[2][BN * APITCH];

    const int tid  = threadIdx.x;
    const int bm   = blockIdx.y, bn = blockIdx.x;
    const int wid  = tid >> 5,  lane = tid & 31;
    const int wm   = wid >> 2,  wn = wid & 3;      // 2 x 4 warp grid
    const int g    = lane >> 2, tq = lane & 3;     // mma group / quad thread

    const __nv_bfloat16* gA = g_xb + (size_t)(bm * BM) * D_DIM;
    const __nv_bfloat16* gB = g_wb + (size_t)(bn * BN) * D_DIM;

    auto load_stage = [&](int bufi, int kc) {
        #pragma unroll
        for (int p = 0; p < 2; p++) {
            int idx = tid + p * 256;               // 0..511
            int row = idx >> 2, cg = idx & 3;      // row 0..127, col group 0..3 (8 bf16 each)
            const __nv_bfloat16* srcA = gA + (size_t)row * D_DIM + kc * BK + cg * 8;
            uint32_t dstA = (uint32_t)__cvta_generic_to_shared(&sA[bufi][row * APITCH + cg * 8]);
            asm volatile("cp.async.cg.shared.global [%0], [%1], 16;\n" :: "r"(dstA), "l"(srcA) : "memory");
            const __nv_bfloat16* srcB = gB + (size_t)row * D_DIM + kc * BK + cg * 8;
            uint32_t dstB = (uint32_t)__cvta_generic_to_shared(&sB[bufi][row * APITCH + cg * 8]);
            asm volatile("cp.async.cg.shared.global [%0], [%1], 16;\n" :: "r"(dstB), "l"(srcB) : "memory");
        }
        asm volatile("cp.async.commit_group;\n" ::: "memory");
    };

    float acc[4][4][4];
    #pragma unroll
    for (int a = 0; a < 4; a++)
        #pragma unroll
        for (int b = 0; b < 4; b++)
            #pragma unroll
            for (int c = 0; c < 4; c++) acc[a][b][c] = 0.0f;

    load_stage(0, 0);

    const int NKC = D_DIM / BK;   // 8
    for (int kc = 0; kc < NKC; kc++) {
        if (kc + 1 < NKC) {
            load_stage((kc + 1) & 1, kc + 1);
            asm volatile("cp.async.wait_group 1;\n" ::: "memory");
        } else {
            asm volatile("cp.async.wait_group 0;\n" ::: "memory");
        }
        __syncthreads();
        const int buf = kc & 1;

        #pragma unroll
        for (int ks = 0; ks < 2; ks++) {
            uint32_t a_frag[4][4];
            #pragma unroll
            for (int mt = 0; mt < 4; mt++) {
                const __nv_bfloat16* p = &sA[buf][(wm * 64 + mt * 16 + g) * APITCH + ks * 16 + tq * 2];
                a_frag[mt][0] = *(const uint32_t*)(p);
                a_frag[mt][1] = *(const uint32_t*)(p + 8 * APITCH);
                a_frag[mt][2] = *(const uint32_t*)(p + 8);
                a_frag[mt][3] = *(const uint32_t*)(p + 8 * APITCH + 8);
            }
            uint32_t b_frag[4][2];
            #pragma unroll
            for (int nt = 0; nt < 4; nt++) {
                const __nv_bfloat16* p = &sB[buf][(wn * 32 + nt * 8 + g) * APITCH + ks * 16 + tq * 2];
                b_frag[nt][0] = *(const uint32_t*)(p);
                b_frag[nt][1] = *(const uint32_t*)(p + 8);
            }
            #pragma unroll
            for (int mt = 0; mt < 4; mt++) {
                #pragma unroll
                for (int nt = 0; nt < 4; nt++) {
                    float* c = acc[mt][nt];
                    asm volatile(
                        "mma.sync.aligned.m16n8k16.row.col.f32.bf16.bf16.f32 "
                        "{%0,%1,%2,%3}, {%4,%5,%6,%7}, {%8,%9}, {%0,%1,%2,%3};\n"
                        : "+f"(c[0]), "+f"(c[1]), "+f"(c[2]), "+f"(c[3])
                        : "r"(a_frag[mt][0]), "r"(a_frag[mt][1]), "r"(a_frag[mt][2]), "r"(a_frag[mt][3]),
                          "r"(b_frag[nt][0]), "r"(b_frag[nt][1]));
                }
            }
        }
        __syncthreads();
    }

    // epilogue: + b_enc, store bf16 acts
    #pragma unroll
    for (int nt = 0; nt < 4; nt++) {
        const int col = bn * BN + wn * 32 + nt * 8 + tq * 2;
        const float be0 = b_enc[col], be1 = b_enc[col + 1];
        #pragma unroll
        for (int mt = 0; mt < 4; mt++) {
            const int r0 = bm * BM + wm * 64 + mt * 16 + g;
            __nv_bfloat162* o0 = (__nv_bfloat162*)(g_acts + (size_t)r0 * H_DIM + col);
            *o0 = __floats2bfloat162_rn(acc[mt][nt][0] + be0, acc[mt][nt][1] + be1);
            __nv_bfloat162* o1 = (__nv_bfloat162*)(g_acts + (size_t)(r0 + 8) * H_DIM + col);
            *o1 = __floats2bfloat162_rn(acc[mt][nt][2] + be0, acc[mt][nt][3] + be1);
        }
    }
}

// ---------------- K2: top-64 candidates -> cublas-order exact recompute -> top-32 -> decode ----------------
__global__ void __launch_bounds__(256) topk_decode_kernel(
    const float* __restrict__ x, const float* __restrict__ W_enc,
    const float* __restrict__ b_enc, const float* __restrict__ W_dec,
    const float* __restrict__ b_dec, float* __restrict__ out)
{
    // per-warp smem: x row (256 f32) + W staging (32 rows x 33 f32, conflict-free pitch)
    __shared__ float sx[8][256];        // 8 KB
    __shared__ float sw[8][32 * 33];    // 33.75 KB

    const int wid  = threadIdx.x >> 5;
    const int lane = threadIdx.x & 31;
    const int b    = blockIdx.x * 8 + wid;
    if (b >= B_TOK) return;

    // ---- phase 1: distributed approx top-64 (2 slots/lane) from bf16 acts ----
    float v0, v1; int i0, i1;
    float thr;
    const uint4* arow = (const uint4*)(g_acts + (size_t)b * H_DIM);
    float f[8];

    auto unpack = [&](uint4 pk) {
        f[0] = __uint_as_float(pk.x << 16); f[1] = __uint_as_float(pk.x & 0xffff0000u);
        f[2] = __uint_as_float(pk.y << 16); f[3] = __uint_as_float(pk.y & 0xffff0000u);
        f[4] = __uint_as_float(pk.z << 16); f[5] = __uint_as_float(pk.z & 0xffff0000u);
        f[6] = __uint_as_float(pk.w << 16); f[7] = __uint_as_float(pk.w & 0xffff0000u);
    };

    auto insert = [&](float cv, int ci) {
        float lmin; int lslot;
        if (v0 <= v1) { lmin = v0; lslot = 0; } else { lmin = v1; lslot = 1; }
        float mval = lmin; int mlan = lane;
        #pragma unroll
        for (int o = 16; o; o >>= 1) {
            float ov = __shfl_xor_sync(0xffffffffu, mval, o);
            int   ol = __shfl_xor_sync(0xffffffffu, mlan, o);
            if (ov < mval || (ov == mval && ol < mlan)) { mval = ov; mlan = ol; }
        }
        if (cv > mval && lane == mlan) {
            if (lslot == 0) { v0 = cv; i0 = ci; } else { v1 = cv; i1 = ci; }
        }
        thr = mval;   // valid lower bound on new min
    };

    {
        uint4 pk = arow[lane];
        unpack(pk);
        int baseidx = lane * 8;
        v0 = f[0]; i0 = baseidx; v1 = f[1]; i1 = baseidx + 1;
        thr = fminf(v0, v1);
        #pragma unroll
        for (int o = 16; o; o >>= 1) thr = fminf(thr, __shfl_xor_sync(0xffffffffu, thr, o));
        for (int j = 2; j < 8; j++) {
            unsigned m = __ballot_sync(0xffffffffu, f[j] > thr);
            while (m) {
                int src = __ffs(m) - 1; m &= m - 1;
                float cv = __shfl_sync(0xffffffffu, f[j], src);
                int   ci = __shfl_sync(0xffffffffu, baseidx + j, src);
                insert(cv, ci);
            }
        }
    }
    for (int it = 1; it < H_DIM / 256; it++) {
        uint4 pk = arow[it * 32 + lane];
        unpack(pk);
        int baseidx = it * 256 + lane * 8;
        #pragma unroll
        for (int j = 0; j < 8; j++) {
            unsigned m = __ballot_sync(0xffffffffu, f[j] > thr);
            while (m) {
                int src = __ffs(m) - 1; m &= m - 1;
                float cv = __shfl_sync(0xffffffffu, f[j], src);
                int   ci = __shfl_sync(0xffffffffu, baseidx + j, src);
                insert(cv, ci);
            }
        }
    }

    // ---- phase 2: exact recompute in cublas order (single-acc sequential FMA, k ascending) ----
    // stage x row (fp32)
    {
        const float4* xp = (const float4*)(x + (size_t)b * D_DIM);
        #pragma unroll
        for (int q = 0; q < 2; q++) {
            float4 v = xp[lane + q * 32];
            float* d = &sx[wid][(lane + q * 32) * 4];
            d[0] = v.x; d[1] = v.y; d[2] = v.z; d[3] = v.w;
        }
        __syncwarp();
    }

    #pragma unroll
    for (int g2 = 0; g2 < 2; g2++) {
        const int myci = g2 ? i1 : i0;
        float acc = 0.0f;
        for (int ch = 0; ch < 8; ch++) {           // 8 chunks of 32 k
            // cooperative, coalesced stage of all 32 lanes' candidate-row chunks
            const int r = (lane >> 3);             // 0..3 base row per pass
            const int c = lane & 7;                // float4 within chunk
            #pragma unroll
            for (int p = 0; p < 8; p++) {
                int row = p * 4 + r;
                int crow = __shfl_sync(0xffffffffu, myci, row);
                float4 v = *(const float4*)(W_enc + (size_t)crow * D_DIM + ch * 32 + c * 4);
                float* dst = &sw[wid][row * 33 + c * 4];
                dst[0] = v.x; dst[1] = v.y; dst[2] = v.z; dst[3] = v.w;   // scalar STS, conflict-free
            }
            __syncwarp();
            const float* wrow = &sw[wid][lane * 33];    // bank = (lane + k) % 32, conflict-free
            const float* xch  = &sx[wid][ch * 32];      // uniform -> broadcast
            #pragma unroll
            for (int k = 0; k < 32; k++)
                acc = fmaf(xch[k], wrow[k], acc);       // strict ascending-k chain
            __syncwarp();
        }
        float d = fmaxf(acc + b_enc[myci], 0.0f);
        if (g2 == 0) v0 = d; else v1 = d;
    }

    // ---- phase 3: exact top-32 extraction (value desc, index asc tiebreak) fused with decode ----
    float acc[8] = {0, 0, 0, 0, 0, 0, 0, 0};
    for (int t = 0; t < K_TOP; t++) {
        float mv; int ms, mi;
        if (v0 > v1 || (v0 == v1 && i0 <= i1)) { mv = v0; ms = 0; mi = i0; }
        else                                   { mv = v1; ms = 1; mi = i1; }
        int ml = lane;
        #pragma unroll
        for (int o = 16; o; o >>= 1) {
            float ov = __shfl_xor_sync(0xffffffffu, mv, o);
            int   oi = __shfl_xor_sync(0xffffffffu, mi, o);
            int   ol = __shfl_xor_sync(0xffffffffu, ml, o);
            int   os = __shfl_xor_sync(0xffffffffu, ms, o);
            if (ov > mv || (ov == mv && oi < mi)) { mv = ov; mi = oi; ml = ol; ms = os; }
        }
        if (lane == ml) { if (ms) v1 = -1e30f; else v0 = -1e30f; }

        const float4* dp = (const float4*)(W_dec + (size_t)mi * D_DIM + lane * 8);
        float4 d0 = dp[0], d1 = dp[1];
        acc[0] = fmaf(mv, d0.x, acc[0]); acc[1] = fmaf(mv, d0.y, acc[1]);
        acc[2] = fmaf(mv, d0.z, acc[2]); acc[3] = fmaf(mv, d0.w, acc[3]);
        acc[4] = fmaf(mv, d1.x, acc[4]); acc[5] = fmaf(mv, d1.y, acc[5]);
        acc[6] = fmaf(mv, d1.z, acc[6]); acc[7] = fmaf(mv, d1.w, acc[7]);
    }

    const float4* bdp = (const float4*)(b_dec + lane * 8);
    float4 bd0 = bdp[0], bd1 = bdp[1];
    float4* op = (float4*)(out + (size_t)b * D_DIM + lane * 8);
    op[0] = make_float4(acc[0] + bd0.x, acc[1] + bd0.y, acc[2] + bd0.z, acc[3] + bd0.w);
    op[1] = make_float4(acc[4] + bd1.x, acc[5] + bd1.y, acc[6] + bd1.z, acc[7] + bd1.w);
}

// ---------------- launch ----------------
extern "C" void kernel_launch(void* const* d_in, const int* in_sizes, int n_in,
                              void* d_out, int out_size) {
    const float* x     = (const float*)d_in[0];
    const float* W_enc = (const float*)d_in[1];
    const float* b_enc = (const float*)d_in[2];
    const float* W_dec = (const float*)d_in[3];
    const float* b_dec = (const float*)d_in[4];
    float* out = (float*)d_out;

    const long long nv = ((long long)B_TOK * D_DIM + (long long)H_DIM * D_DIM) / 4;
    cvt_kernel<<<(int)((nv + 255) / 256), 256>>>(x, W_enc);

    dim3 ggrid(H_DIM / BN, B_TOK / BM);
    enc_gemm_kernel<<<ggrid, 256>>>(b_enc);

    topk_decode_kernel<<<B_TOK / 8, 256>>>(x, W_enc, b_enc, W_dec, b_dec, out);
}

// round 5
// speedup vs baseline: 1.1500x; 1.1500x over previous
#include <cuda_runtime.h>
#include <cuda_bf16.h>
#include <cstdint>

#define B_TOK 32768
#define D_DIM 256
#define H_DIM 8192
#define K_TOP 32
#define CAP   384

// ---------------- static scratch (no cudaMalloc allowed) ----------------
__device__ __align__(16) __nv_bfloat16 g_xb[(size_t)B_TOK * D_DIM];          // 16 MB
__device__ __align__(16) __nv_bfloat16 g_wb[(size_t)H_DIM * D_DIM];          //  4 MB
__device__ __align__(16) unsigned long long g_cand[(size_t)B_TOK * CAP];     // 100 MB
__device__ int   g_cnt[B_TOK];
__device__ float g_tau[B_TOK];

// ---------------- K00: zero counters ----------------
__global__ void zero_kernel() {
    int i = blockIdx.x * blockDim.x + threadIdx.x;
    if (i < B_TOK) g_cnt[i] = 0;
}

// ---------------- K01: per-token threshold tau = 2.15 * 0.02 * ||x|| ----------------
__global__ void tau_kernel(const float* __restrict__ x) {
    const int wid  = threadIdx.x >> 5;
    const int lane = threadIdx.x & 31;
    const int b    = blockIdx.x * 8 + wid;
    if (b >= B_TOK) return;
    const float4* xp = (const float4*)(x + (size_t)b * D_DIM);
    float4 u0 = xp[lane], u1 = xp[lane + 32];
    float s = u0.x*u0.x + u0.y*u0.y + u0.z*u0.z + u0.w*u0.w
            + u1.x*u1.x + u1.y*u1.y + u1.z*u1.z + u1.w*u1.w;
    #pragma unroll
    for (int o = 16; o; o >>= 1) s += __shfl_xor_sync(0xffffffffu, s, o);
    if (lane == 0) g_tau[b] = 0.0430f * sqrtf(s);
}

// ---------------- K0: fp32 -> bf16 conversion ----------------
__global__ void cvt_kernel(const float* __restrict__ x, const float* __restrict__ w) {
    const long long n1 = (long long)B_TOK * D_DIM / 4;
    const long long n2 = (long long)H_DIM * D_DIM / 4;
    long long i = blockIdx.x * (long long)blockDim.x + threadIdx.x;
    if (i < n1) {
        float4 v = ((const float4*)x)[i];
        __nv_bfloat162* o = (__nv_bfloat162*)g_xb;
        o[2 * i]     = __floats2bfloat162_rn(v.x, v.y);
        o[2 * i + 1] = __floats2bfloat162_rn(v.z, v.w);
    } else if (i < n1 + n2) {
        long long j = i - n1;
        float4 v = ((const float4*)w)[j];
        __nv_bfloat162* o = (__nv_bfloat162*)g_wb;
        o[2 * j]     = __floats2bfloat162_rn(v.x, v.y);
        o[2 * j + 1] = __floats2bfloat162_rn(v.z, v.w);
    }
}

// ---------------- K1: bf16 GEMM + threshold-compact epilogue ----------------
#define BM 128
#define BN 128
#define BK 32
#define APITCH 40

__global__ void __launch_bounds__(256, 2) enc_gemm_kernel(const float* __restrict__ b_enc) {
    __shared__ __align__(16) __nv_bfloat16 sA[2][BM * APITCH];
    __shared__ __align__(16) __nv_bfloat16 sB[2][BN * APITCH];

    const int tid  = threadIdx.x;
    const int bm   = blockIdx.y, bn = blockIdx.x;
    const int wid  = tid >> 5,  lane = tid & 31;
    const int wm   = wid >> 2,  wn = wid & 3;
    const int g    = lane >> 2, tq = lane & 3;

    const __nv_bfloat16* gA = g_xb + (size_t)(bm * BM) * D_DIM;
    const __nv_bfloat16* gB = g_wb + (size_t)(bn * BN) * D_DIM;

    auto load_stage = [&](int bufi, int kc) {
        #pragma unroll
        for (int p = 0; p < 2; p++) {
            int idx = tid + p * 256;
            int row = idx >> 2, cg = idx & 3;
            const __nv_bfloat16* srcA = gA + (size_t)row * D_DIM + kc * BK + cg * 8;
            uint32_t dstA = (uint32_t)__cvta_generic_to_shared(&sA[bufi][row * APITCH + cg * 8]);
            asm volatile("cp.async.cg.shared.global [%0], [%1], 16;\n" :: "r"(dstA), "l"(srcA) : "memory");
            const __nv_bfloat16* srcB = gB + (size_t)row * D_DIM + kc * BK + cg * 8;
            uint32_t dstB = (uint32_t)__cvta_generic_to_shared(&sB[bufi][row * APITCH + cg * 8]);
            asm volatile("cp.async.cg.shared.global [%0], [%1], 16;\n" :: "r"(dstB), "l"(srcB) : "memory");
        }
        asm volatile("cp.async.commit_group;\n" ::: "memory");
    };

    float acc[4][4][4];
    #pragma unroll
    for (int a = 0; a < 4; a++)
        #pragma unroll
        for (int b2 = 0; b2 < 4; b2++)
            #pragma unroll
            for (int c = 0; c < 4; c++) acc[a][b2][c] = 0.0f;

    load_stage(0, 0);

    const int NKC = D_DIM / BK;
    for (int kc = 0; kc < NKC; kc++) {
        if (kc + 1 < NKC) {
            load_stage((kc + 1) & 1, kc + 1);
            asm volatile("cp.async.wait_group 1;\n" ::: "memory");
        } else {
            asm volatile("cp.async.wait_group 0;\n" ::: "memory");
        }
        __syncthreads();
        const int buf = kc & 1;

        #pragma unroll
        for (int ks = 0; ks < 2; ks++) {
            uint32_t a_frag[4][4];
            #pragma unroll
            for (int mt = 0; mt < 4; mt++) {
                const __nv_bfloat16* p = &sA[buf][(wm * 64 + mt * 16 + g) * APITCH + ks * 16 + tq * 2];
                a_frag[mt][0] = *(const uint32_t*)(p);
                a_frag[mt][1] = *(const uint32_t*)(p + 8 * APITCH);
                a_frag[mt][2] = *(const uint32_t*)(p + 8);
                a_frag[mt][3] = *(const uint32_t*)(p + 8 * APITCH + 8);
            }
            uint32_t b_frag[4][2];
            #pragma unroll
            for (int nt = 0; nt < 4; nt++) {
                const __nv_bfloat16* p = &sB[buf][(wn * 32 + nt * 8 + g) * APITCH + ks * 16 + tq * 2];
                b_frag[nt][0] = *(const uint32_t*)(p);
                b_frag[nt][1] = *(const uint32_t*)(p + 8);
            }
            #pragma unroll
            for (int mt = 0; mt < 4; mt++) {
                #pragma unroll
                for (int nt = 0; nt < 4; nt++) {
                    float* c = acc[mt][nt];
                    asm volatile(
                        "mma.sync.aligned.m16n8k16.row.col.f32.bf16.bf16.f32 "
                        "{%0,%1,%2,%3}, {%4,%5,%6,%7}, {%8,%9}, {%0,%1,%2,%3};\n"
                        : "+f"(c[0]), "+f"(c[1]), "+f"(c[2]), "+f"(c[3])
                        : "r"(a_frag[mt][0]), "r"(a_frag[mt][1]), "r"(a_frag[mt][2]), "r"(a_frag[mt][3]),
                          "r"(b_frag[nt][0]), "r"(b_frag[nt][1]));
                }
            }
        }
        __syncthreads();
    }

    // epilogue: threshold-compact candidates (no acts store)
    auto emit = [&](float v, int row, int col, float tau) {
        if (v > tau) {
            int p = atomicAdd(&g_cnt[row], 1);
            if (p < CAP)
                g_cand[(size_t)row * CAP + p] =
                    ((unsigned long long)__float_as_uint(v) << 32) | (unsigned)col;
        }
    };
    #pragma unroll
    for (int mt = 0; mt < 4; mt++) {
        const int r0 = bm * BM + wm * 64 + mt * 16 + g;
        const int r1 = r0 + 8;
        const float t0 = g_tau[r0], t1 = g_tau[r1];
        #pragma unroll
        for (int nt = 0; nt < 4; nt++) {
            const int col = bn * BN + wn * 32 + nt * 8 + tq * 2;
            const float be0 = b_enc[col], be1 = b_enc[col + 1];
            emit(acc[mt][nt][0] + be0, r0, col,     t0);
            emit(acc[mt][nt][1] + be1, r0, col + 1, t0);
            emit(acc[mt][nt][2] + be0, r1, col,     t1);
            emit(acc[mt][nt][3] + be1, r1, col + 1, t1);
        }
    }
}

// ---------------- K2: candidates -> top-64 -> exact recompute -> top-32 -> decode ----------------
#define SWP 36   // smem W pitch (floats): 16B-aligned rows, bounded conflicts

__global__ void __launch_bounds__(256) topk_decode_kernel(
    const float* __restrict__ x, const float* __restrict__ W_enc,
    const float* __restrict__ b_enc, const float* __restrict__ W_dec,
    const float* __restrict__ b_dec, float* __restrict__ out)
{
    __shared__ __align__(16) float sx[8][256];
    __shared__ __align__(16) float sw[8][32 * SWP];

    const int wid  = threadIdx.x >> 5;
    const int lane = threadIdx.x & 31;
    const int b    = blockIdx.x * 8 + wid;
    if (b >= B_TOK) return;

    // stage x row (fp32) -- used by both paths
    {
        const float4* xp = (const float4*)(x + (size_t)b * D_DIM);
        #pragma unroll
        for (int q = 0; q < 2; q++) {
            float4 v = xp[lane + q * 32];
            float* d = &sx[wid][(lane + q * 32) * 4];
            d[0] = v.x; d[1] = v.y; d[2] = v.z; d[3] = v.w;
        }
        __syncwarp();
    }

    const int c = g_cnt[b];
    const bool bad = (c < K_TOP) || (c > CAP);

    float v0, v1; int i0, i1;
    bool valid1;

    // exact sequential-chain dot of staged x with one staged W row chunk set
    auto chain8 = [&](float& accv, int ch) {
        const float4* wr = (const float4*)&sw[wid][lane * SWP];
        const float4* xc = (const float4*)&sx[wid][ch * 32];
        #pragma unroll
        for (int s = 0; s < 8; s++) {
            float4 wv = wr[s];
            float4 xv = xc[s];
            accv = fmaf(xv.x, wv.x, accv);
            accv = fmaf(xv.y, wv.y, accv);
            accv = fmaf(xv.z, wv.z, accv);
            accv = fmaf(xv.w, wv.w, accv);
        }
    };

    if (!bad) {
        // ---- load first 64 candidates into 2 slots/lane ----
        {
            unsigned long long p0 = g_cand[(size_t)b * CAP + lane];
            v0 = __uint_as_float((unsigned)(p0 >> 32)); i0 = (int)(unsigned)p0;
        }
        valid1 = (32 + lane) < c;
        if (valid1) {
            unsigned long long p1 = g_cand[(size_t)b * CAP + 32 + lane];
            v1 = __uint_as_float((unsigned)(p1 >> 32)); i1 = (int)(unsigned)p1;
        } else { v1 = -1e30f; i1 = 0; }

        float thr = fminf(v0, v1);
        #pragma unroll
        for (int o = 16; o; o >>= 1) thr = fminf(thr, __shfl_xor_sync(0xffffffffu, thr, o));

        auto insert = [&](float cv, int ci) {
            float lmin; int lslot;
            if (v0 <= v1) { lmin = v0; lslot = 0; } else { lmin = v1; lslot = 1; }
            float mval = lmin; int mlan = lane;
            #pragma unroll
            for (int o = 16; o; o >>= 1) {
                float ov = __shfl_xor_sync(0xffffffffu, mval, o);
                int   ol = __shfl_xor_sync(0xffffffffu, mlan, o);
                if (ov < mval || (ov == mval && ol < mlan)) { mval = ov; mlan = ol; }
            }
            if (cv > mval && lane == mlan) {
                if (lslot == 0) { v0 = cv; i0 = ci; } else { v1 = cv; i1 = ci; }
            }
            thr = mval;
        };

        // ---- stream remaining candidates ----
        for (int base = 64; base < c; base += 32) {
            float cv = -1e30f; int ci = 0;
            if (base + lane < c) {
                unsigned long long pk = g_cand[(size_t)b * CAP + base + lane];
                cv = __uint_as_float((unsigned)(pk >> 32)); ci = (int)(unsigned)pk;
            }
            unsigned m = __ballot_sync(0xffffffffu, cv > thr);
            while (m) {
                int src = __ffs(m) - 1; m &= m - 1;
                float xv = __shfl_sync(0xffffffffu, cv, src);
                int   xi = __shfl_sync(0xffffffffu, ci, src);
                if (xv > thr) insert(xv, xi);
            }
        }
        // after streaming, slot validity: any slot that was replaced is valid;
        // untouched pad slots still hold -1e30f. Track v1 pads by value.
        valid1 = valid1 || (v1 > -1e29f);

        // ---- exact recompute (cublas chain order) for the 64 slots ----
        #pragma unroll
        for (int g2 = 0; g2 < 2; g2++) {
            const int myci = g2 ? i1 : i0;
            float accv = 0.0f;
            for (int ch = 0; ch < 8; ch++) {
                const int r = lane >> 3, cc = lane & 7;
                #pragma unroll
                for (int p = 0; p < 8; p++) {
                    int row  = p * 4 + r;
                    int crow = __shfl_sync(0xffffffffu, myci, row);
                    float4 v = *(const float4*)(W_enc + (size_t)crow * D_DIM + ch * 32 + cc * 4);
                    *(float4*)&sw[wid][row * SWP + cc * 4] = v;
                }
                __syncwarp();
                chain8(accv, ch);
                __syncwarp();
            }
            float d = fmaxf(accv + b_enc[myci], 0.0f);
            if (g2 == 0) v0 = d;
            else         v1 = valid1 ? d : -1e30f;
        }
    } else {
        // ---- fallback: exact brute force over all H (never expected) ----
        float fv = -1e30f; int fi = 0; float thr32 = -1e30f;
        for (int stage = 0; stage < H_DIM / 32; stage++) {
            float accv = 0.0f;
            for (int ch = 0; ch < 8; ch++) {
                const int r = lane >> 3, cc = lane & 7;
                #pragma unroll
                for (int p = 0; p < 8; p++) {
                    int row  = p * 4 + r;
                    int crow = stage * 32 + row;
                    float4 v = *(const float4*)(W_enc + (size_t)crow * D_DIM + ch * 32 + cc * 4);
                    *(float4*)&sw[wid][row * SWP + cc * 4] = v;
                }
                __syncwarp();
                chain8(accv, ch);
                __syncwarp();
            }
            float d  = fmaxf(accv + b_enc[stage * 32 + lane], 0.0f);
            int   di = stage * 32 + lane;
            unsigned m = __ballot_sync(0xffffffffu, d > thr32);
            while (m) {
                int src = __ffs(m) - 1; m &= m - 1;
                float cv = __shfl_sync(0xffffffffu, d, src);
                int   ci = __shfl_sync(0xffffffffu, di, src);
                float mval = fv; int mlan = lane;
                #pragma unroll
                for (int o = 16; o; o >>= 1) {
                    float ov = __shfl_xor_sync(0xffffffffu, mval, o);
                    int   ol = __shfl_xor_sync(0xffffffffu, mlan, o);
                    if (ov < mval || (ov == mval && ol < mlan)) { mval = ov; mlan = ol; }
                }
                if (cv > mval && lane == mlan) { fv = cv; fi = ci; }
                thr32 = mval;
            }
        }
        v0 = fv; i0 = fi; v1 = -1e30f; i1 = 0;
    }

    // ---- exact top-32 extraction (value desc, index asc) fused with decode ----
    float acc[8] = {0, 0, 0, 0, 0, 0, 0, 0};
    for (int t = 0; t < K_TOP; t++) {
        float mv; int ms, mi;
        if (v0 > v1 || (v0 == v1 && i0 <= i1)) { mv = v0; ms = 0; mi = i0; }
        else                                   { mv = v1; ms = 1; mi = i1; }
        int ml = lane;
        #pragma unroll
        for (int o = 16; o; o >>= 1) {
            float ov = __shfl_xor_sync(0xffffffffu, mv, o);
            int   oi = __shfl_xor_sync(0xffffffffu, mi, o);
            int   ol = __shfl_xor_sync(0xffffffffu, ml, o);
            int   os = __shfl_xor_sync(0xffffffffu, ms, o);
            if (ov > mv || (ov == mv && oi < mi)) { mv = ov; mi = oi; ml = ol; ms = os; }
        }
        if (lane == ml) { if (ms) v1 = -1e30f; else v0 = -1e30f; }

        const float4* dp = (const float4*)(W_dec + (size_t)mi * D_DIM + lane * 8);
        float4 d0 = dp[0], d1 = dp[1];
        acc[0] = fmaf(mv, d0.x, acc[0]); acc[1] = fmaf(mv, d0.y, acc[1]);
        acc[2] = fmaf(mv, d0.z, acc[2]); acc[3] = fmaf(mv, d0.w, acc[3]);
        acc[4] = fmaf(mv, d1.x, acc[4]); acc[5] = fmaf(mv, d1.y, acc[5]);
        acc[6] = fmaf(mv, d1.z, acc[6]); acc[7] = fmaf(mv, d1.w, acc[7]);
    }

    const float4* bdp = (const float4*)(b_dec + lane * 8);
    float4 bd0 = bdp[0], bd1 = bdp[1];
    float4* op = (float4*)(out + (size_t)b * D_DIM + lane * 8);
    op[0] = make_float4(acc[0] + bd0.x, acc[1] + bd0.y, acc[2] + bd0.z, acc[3] + bd0.w);
    op[1] = make_float4(acc[4] + bd1.x, acc[5] + bd1.y, acc[6] + bd1.z, acc[7] + bd1.w);
}

// ---------------- launch ----------------
extern "C" void kernel_launch(void* const* d_in, const int* in_sizes, int n_in,
                              void* d_out, int out_size) {
    const float* x     = (const float*)d_in[0];
    const float* W_enc = (const float*)d_in[1];
    const float* b_enc = (const float*)d_in[2];
    const float* W_dec = (const float*)d_in[3];
    const float* b_dec = (const float*)d_in[4];
    float* out = (float*)d_out;

    zero_kernel<<<(B_TOK + 255) / 256, 256>>>();
    tau_kernel<<<B_TOK / 8, 256>>>(x);

    const long long nv = ((long long)B_TOK * D_DIM + (long long)H_DIM * D_DIM) / 4;
    cvt_kernel<<<(int)((nv + 255) / 256), 256>>>(x, W_enc);

    dim3 ggrid(H_DIM / BN, B_TOK / BM);
    enc_gemm_kernel<<<ggrid, 256>>>(b_enc);

    topk_decode_kernel<<<B_TOK / 8, 256>>>(x, W_enc, b_enc, W_dec, b_dec, out);
}